// round 16
// baseline (speedup 1.0000x reference)
#include <cuda_runtime.h>
#include <cuda_bf16.h>
#include <cstdint>

#define B_SZ   2048
#define N_INST 8
#define N_FEAT 100
#define N_HID  40
#define NM     41
#define NC     40
#define NTHR   512

#define IMGA_C 17920
#define IMGB_C 19968

// ---- smem map (bytes) ----
#define SM_XS    0                 // X bf16 [129][112] hi+lo = 57792
#define XS_LO    28896
#define SM_HA    57792             // h accum f32 [129][40] = 20640
#define SM_HS    78432             // h bf16 [129][48] hi+lo = 24768
#define HS_LO    12384
#define SM_OS    103200            // out accum f32 [129][104] = 53664
#define SM_RL    156864            // rowlists u8 [40][144] = 5760
#define SM_TL    162624            // tile list u16[512] = 1024
#define SM_CNT   163648            // int[41] (CNT + NT), padded
#define SM_BIAS  163840            // 16-aligned (FIX: was 163812, broke float2 loads)
#define SM_TOTAL 164352

__device__ __align__(16) unsigned char g_imgA[N_INST * NC * IMGA_C];
__device__ __align__(16) unsigned char g_imgB[N_INST * NC * IMGB_C];

// ===================== helpers =====================
__device__ __forceinline__ uint32_t smem_u32(const void* p) {
    return (uint32_t)__cvta_generic_to_shared(p);
}
__device__ __forceinline__ void mma_bf16(float* d, const uint32_t* a, uint32_t b0, uint32_t b1) {
    asm volatile("mma.sync.aligned.m16n8k16.row.col.f32.bf16.bf16.f32 "
                 "{%0,%1,%2,%3},{%4,%5,%6,%7},{%8,%9},{%0,%1,%2,%3};"
                 : "+f"(d[0]), "+f"(d[1]), "+f"(d[2]), "+f"(d[3])
                 : "r"(a[0]), "r"(a[1]), "r"(a[2]), "r"(a[3]), "r"(b0), "r"(b1));
}
__device__ __forceinline__ void mma_bf16_k8(float* d, uint32_t a0, uint32_t a1, uint32_t b0) {
    asm volatile("mma.sync.aligned.m16n8k8.row.col.f32.bf16.bf16.f32 "
                 "{%0,%1,%2,%3},{%4,%5},{%6},{%0,%1,%2,%3};"
                 : "+f"(d[0]), "+f"(d[1]), "+f"(d[2]), "+f"(d[3])
                 : "r"(a0), "r"(a1), "r"(b0));
}
__device__ __forceinline__ void ldm_x4(uint32_t* r, uint32_t a) {
    asm volatile("ldmatrix.sync.aligned.m8n8.x4.shared.b16 {%0,%1,%2,%3}, [%4];"
                 : "=r"(r[0]), "=r"(r[1]), "=r"(r[2]), "=r"(r[3]) : "r"(a));
}
__device__ __forceinline__ void ldm_x2(uint32_t* r, uint32_t a) {
    asm volatile("ldmatrix.sync.aligned.m8n8.x2.shared.b16 {%0,%1}, [%2];"
                 : "=r"(r[0]), "=r"(r[1]) : "r"(a));
}
__device__ __forceinline__ uint32_t pack_bf2(float a, float b) {
    __nv_bfloat162 t = __floats2bfloat162_rn(a, b);
    return *reinterpret_cast<uint32_t*>(&t);
}
__device__ __forceinline__ void split_pair(float a, float b, uint32_t& hi, uint32_t& lo) {
    const __nv_bfloat16 ah = __float2bfloat16(a), bh = __float2bfloat16(b);
    hi = pack_bf2(a, b);
    lo = pack_bf2(a - __bfloat162float(ah), b - __bfloat162float(bh));
}
__device__ __forceinline__ uint4 frag_word(float v00, float v01, float v10, float v11) {
    uint4 w; uint32_t h0, l0, h1, l1;
    split_pair(v00, v01, h0, l0);
    split_pair(v10, v11, h1, l1);
    w.x = h0; w.y = h1; w.z = l0; w.w = l1;
    return w;
}

// ===================== Kernel 1: G -> fragment images =====================
__global__ __launch_bounds__(256)
void compute_G_kernel(const float* __restrict__ A, const float* __restrict__ Bp) {
    __shared__ float AsT[NM * N_FEAT];
    __shared__ float Bs[NM * N_HID];
    __shared__ float sS[N_FEAT * N_HID];
    const int ic = blockIdx.x;
    const float* Ap  = A  + (size_t)ic * N_FEAT * NM;
    const float* Bpp = Bp + (size_t)ic * NM * N_HID;
    uint4* iA = reinterpret_cast<uint4*>(g_imgA + (size_t)ic * IMGA_C);
    uint4* iB = reinterpret_cast<uint4*>(g_imgB + (size_t)ic * IMGB_C);

    for (int idx = threadIdx.x; idx < N_FEAT * NM; idx += blockDim.x) {
        const int f = idx / NM, m = idx % NM;
        AsT[m * N_FEAT + f] = Ap[idx];
    }
    for (int idx = threadIdx.x; idx < NM * N_HID; idx += blockDim.x) Bs[idx] = Bpp[idx];
    __syncthreads();
    for (int t = threadIdx.x; t < 1000; t += blockDim.x) {
        const int fp = t / 20, hp = t % 20;
        float a00 = 0.f, a01 = 0.f, a10 = 0.f, a11 = 0.f;
#pragma unroll
        for (int m = 0; m < NM; m++) {
            const float2 a = *reinterpret_cast<const float2*>(&AsT[m * N_FEAT + fp * 2]);
            const float2 b = *reinterpret_cast<const float2*>(&Bs[m * N_HID + hp * 2]);
            a00 = fmaf(a.x, b.x, a00); a01 = fmaf(a.x, b.y, a01);
            a10 = fmaf(a.y, b.x, a10); a11 = fmaf(a.y, b.y, a11);
        }
        *reinterpret_cast<float2*>(&sS[(fp * 2)     * N_HID + hp * 2]) = make_float2(a00, a01);
        *reinterpret_cast<float2*>(&sS[(fp * 2 + 1) * N_HID + hp * 2]) = make_float2(a10, a11);
    }
    __syncthreads();
    for (int widx = threadIdx.x; widx < 7 * 5 * 32; widx += blockDim.x) {
        const int kst = widx / 160, rem = widx % 160;
        const int nt = rem / 32, T = rem % 32;
        const int q = T & 3, tr = T >> 2;
        const int n = nt * 8 + tr;
        float v[2][2];
#pragma unroll
        for (int half = 0; half < 2; half++)
#pragma unroll
            for (int lo = 0; lo < 2; lo++) {
                const int f = kst * 16 + q * 2 + half * 8 + lo;
                v[half][lo] = (f < N_FEAT) ? sS[f * N_HID + n] : 0.f;
            }
        iA[widx] = frag_word(v[0][0], v[0][1], v[1][0], v[1][1]);
    }
    for (int widx = threadIdx.x; widx < 3 * 13 * 32; widx += blockDim.x) {
        const int kst = widx / 416, rem = widx % 416;
        const int nt = rem / 32, T = rem % 32;
        const int q = T & 3, tr = T >> 2;
        const int f = nt * 8 + tr;
        float v[2][2];
#pragma unroll
        for (int half = 0; half < 2; half++)
#pragma unroll
            for (int lo = 0; lo < 2; lo++) {
                const int h = kst * 16 + q * 2 + half * 8 + lo;
                v[half][lo] = (f < N_FEAT && h < N_HID) ? sS[f * N_HID + h] : 0.f;
            }
        iB[widx] = frag_word(v[0][0], v[0][1], v[1][0], v[1][1]);
    }
}

// ===================== Kernel 2: sparse, gmem B-frags, flat tile loop =====================
__global__ __launch_bounds__(NTHR)
void tmsspd_main_kernel(const float* __restrict__ x, const float* __restrict__ mask,
                        const float* __restrict__ bfin, float* __restrict__ out) {
    extern __shared__ char smem[];
    const uint32_t sb = smem_u32(smem);
    unsigned char* RL = reinterpret_cast<unsigned char*>(smem + SM_RL);
    uint16_t* TL = reinterpret_cast<uint16_t*>(smem + SM_TL);
    int*   CNT   = reinterpret_cast<int*>(smem + SM_CNT);
    float* biasS = reinterpret_cast<float*>(smem + SM_BIAS);
    float* hA = reinterpret_cast<float*>(smem + SM_HA);
    float* oS = reinterpret_cast<float*>(smem + SM_OS);

    const int i   = blockIdx.y;
    const int b0  = blockIdx.x * 128;
    const int tid = threadIdx.x;
    const int w   = tid >> 5;
    const int T   = tid & 31;
    const int q   = T & 3;
    const int jj  = ((T >> 3) & 1) * 8 + (T & 7);
    const int kh  = (T >> 4) * 16;

    const unsigned char* imgA = g_imgA + (size_t)(i * NC) * IMGA_C;
    const unsigned char* imgB = g_imgB + (size_t)(i * NC) * IMGB_C;

    // ---- row lists (warp per c) ----
    for (int c = w; c < NC; c += 16) {
        int base = 0;
#pragma unroll
        for (int ch = 0; ch < 4; ch++) {
            const int r = ch * 32 + T;
            const float m = mask[((size_t)(b0 + r) * N_INST + i) * NC + c];
            const unsigned bal = __ballot_sync(0xffffffffu, m != 0.f);
            const int pos = __popc(bal & ((1u << T) - 1u));
            if (m != 0.f) RL[c * 144 + base + pos] = (unsigned char)r;
            base += __popc(bal);
        }
        const int nt = (base + 15) >> 4;
        for (int j = base + T; j < nt * 16; j += 32) RL[c * 144 + j] = 128;
        if (T == 0) CNT[c] = nt;
    }
    // ---- XS: x bf16 split [129][112] ----
    for (int idx = tid; idx < 129 * 56; idx += NTHR) {
        const int r = idx / 56, kp = idx % 56;
        float2 v = make_float2(0.f, 0.f);
        if (r < 128 && kp < 50)
            v = *reinterpret_cast<const float2*>(&x[((size_t)(b0 + r) * N_INST + i) * N_FEAT + kp * 2]);
        uint32_t hi, lo; split_pair(v.x, v.y, hi, lo);
        *reinterpret_cast<uint32_t*>(smem + SM_XS + r * 224 + kp * 4) = hi;
        *reinterpret_cast<uint32_t*>(smem + SM_XS + XS_LO + r * 224 + kp * 4) = lo;
    }
    for (int idx = tid; idx < 5160; idx += NTHR) hA[idx] = 0.f;
    for (int idx = tid; idx < 13416; idx += NTHR) oS[idx] = 0.f;
    if (tid < N_FEAT) biasS[tid] = bfin[i * N_FEAT + tid];
    __syncthreads();
    if (tid == 0) {               // flat tile list
        int n = 0;
        for (int c = 0; c < NC; c++)
            for (int tt = 0; tt < CNT[c]; tt++) TL[n++] = (uint16_t)(c | (tt << 8));
        CNT[40] = n;
    }
    __syncthreads();
    const int NT = CNT[40];

    // ================= Phase A =================
    for (int t = w; t < NT; t += 16) {
        const int c = TL[t] & 255, tt = TL[t] >> 8;
        const unsigned char* buf = imgA + (size_t)c * IMGA_C;
        const unsigned char* rl = RL + c * 144 + tt * 16;
        const int myrow = rl[jj];
        const uint32_t ab = sb + SM_XS + myrow * 224 + kh;

        float d[5][4];
#pragma unroll
        for (int nt = 0; nt < 5; nt++)
#pragma unroll
            for (int j = 0; j < 4; j++) d[nt][j] = 0.f;

#pragma unroll
        for (int kst = 0; kst < 6; kst++) {
            uint4 wv[5];
#pragma unroll
            for (int nt = 0; nt < 5; nt++)
                wv[nt] = *reinterpret_cast<const uint4*>(buf + (((kst * 5 + nt) * 32 + T) << 4));
            uint32_t ah[4], al[4];
            ldm_x4(ah, ab + kst * 32);
            ldm_x4(al, ab + XS_LO + kst * 32);
#pragma unroll
            for (int nt = 0; nt < 5; nt++) mma_bf16(d[nt], ah, wv[nt].x, wv[nt].y);
#pragma unroll
            for (int nt = 0; nt < 5; nt++) mma_bf16(d[nt], ah, wv[nt].z, wv[nt].w);
#pragma unroll
            for (int nt = 0; nt < 5; nt++) mma_bf16(d[nt], al, wv[nt].x, wv[nt].y);
        }
        {   // k8 tail (f 96..103)
            uint4 wv[5];
#pragma unroll
            for (int nt = 0; nt < 5; nt++)
                wv[nt] = *reinterpret_cast<const uint4*>(buf + (((30 + nt) * 32 + T) << 4));
            uint32_t ah[2], al[2];
            ldm_x2(ah, sb + SM_XS + myrow * 224 + 192);
            ldm_x2(al, sb + SM_XS + XS_LO + myrow * 224 + 192);
#pragma unroll
            for (int nt = 0; nt < 5; nt++) mma_bf16_k8(d[nt], ah[0], ah[1], wv[nt].x);
#pragma unroll
            for (int nt = 0; nt < 5; nt++) mma_bf16_k8(d[nt], ah[0], ah[1], wv[nt].z);
#pragma unroll
            for (int nt = 0; nt < 5; nt++) mma_bf16_k8(d[nt], al[0], al[1], wv[nt].x);
        }
        const int ra = rl[T >> 2], rb = rl[(T >> 2) + 8];
#pragma unroll
        for (int nt = 0; nt < 5; nt++) {
            const int col = nt * 8 + q * 2;
            atomicAdd(&hA[ra * 40 + col],     d[nt][0]);
            atomicAdd(&hA[ra * 40 + col + 1], d[nt][1]);
            atomicAdd(&hA[rb * 40 + col],     d[nt][2]);
            atomicAdd(&hA[rb * 40 + col + 1], d[nt][3]);
        }
    }
    __syncthreads();

    // ---- HS: h bf16 split [129][48] ----
    for (int idx = tid; idx < 129 * 24; idx += NTHR) {
        const int r = idx / 24, kp = idx % 24;
        float2 v = make_float2(0.f, 0.f);
        if (r < 128 && kp < 20)
            v = *reinterpret_cast<const float2*>(&hA[r * 40 + kp * 2]);
        uint32_t hi, lo; split_pair(v.x, v.y, hi, lo);
        *reinterpret_cast<uint32_t*>(smem + SM_HS + r * 96 + kp * 4) = hi;
        *reinterpret_cast<uint32_t*>(smem + SM_HS + HS_LO + r * 96 + kp * 4) = lo;
    }
    __syncthreads();

    // ================= Phase B =================
    for (int t = w; t < NT; t += 16) {
        const int c = TL[t] & 255, tt = TL[t] >> 8;
        const unsigned char* buf = imgB + (size_t)c * IMGB_C;
        const unsigned char* rl = RL + c * 144 + tt * 16;
        const int myrow = rl[jj];
        const uint32_t ab = sb + SM_HS + myrow * 96 + kh;

        float d[13][4];
#pragma unroll
        for (int nt = 0; nt < 13; nt++)
#pragma unroll
            for (int j = 0; j < 4; j++) d[nt][j] = 0.f;

#pragma unroll
        for (int kst = 0; kst < 2; kst++) {
            uint32_t ah[4], al[4];
            ldm_x4(ah, ab + kst * 32);
            ldm_x4(al, ab + HS_LO + kst * 32);
            {
                uint4 wv[7];
#pragma unroll
                for (int j = 0; j < 7; j++)
                    wv[j] = *reinterpret_cast<const uint4*>(buf + (((kst * 13 + j) * 32 + T) << 4));
#pragma unroll
                for (int j = 0; j < 7; j++) mma_bf16(d[j], ah, wv[j].x, wv[j].y);
#pragma unroll
                for (int j = 0; j < 7; j++) mma_bf16(d[j], ah, wv[j].z, wv[j].w);
#pragma unroll
                for (int j = 0; j < 7; j++) mma_bf16(d[j], al, wv[j].x, wv[j].y);
            }
            {
                uint4 wv[6];
#pragma unroll
                for (int j = 0; j < 6; j++)
                    wv[j] = *reinterpret_cast<const uint4*>(buf + (((kst * 13 + 7 + j) * 32 + T) << 4));
#pragma unroll
                for (int j = 0; j < 6; j++) mma_bf16(d[7 + j], ah, wv[j].x, wv[j].y);
#pragma unroll
                for (int j = 0; j < 6; j++) mma_bf16(d[7 + j], ah, wv[j].z, wv[j].w);
#pragma unroll
                for (int j = 0; j < 6; j++) mma_bf16(d[7 + j], al, wv[j].x, wv[j].y);
            }
        }
        {   // k8 tail (h 32..39)
            uint32_t ah[2], al[2];
            ldm_x2(ah, sb + SM_HS + myrow * 96 + 64);
            ldm_x2(al, sb + SM_HS + HS_LO + myrow * 96 + 64);
#pragma unroll
            for (int j = 0; j < 13; j++) {
                const uint4 wv = *reinterpret_cast<const uint4*>(buf + (((26 + j) * 32 + T) << 4));
                mma_bf16_k8(d[j], ah[0], ah[1], wv.x);
                mma_bf16_k8(d[j], ah[0], ah[1], wv.z);
                mma_bf16_k8(d[j], al[0], al[1], wv.x);
            }
        }
        const int ra = rl[T >> 2], rb = rl[(T >> 2) + 8];
#pragma unroll
        for (int nt = 0; nt < 13; nt++) {
            const int col = nt * 8 + q * 2;
            atomicAdd(&oS[ra * 104 + col],     d[nt][0]);
            atomicAdd(&oS[ra * 104 + col + 1], d[nt][1]);
            atomicAdd(&oS[rb * 104 + col],     d[nt][2]);
            atomicAdd(&oS[rb * 104 + col + 1], d[nt][3]);
        }
    }
    __syncthreads();

    // ================= epilogue =================
    for (int idx = tid; idx < 128 * 50; idx += NTHR) {
        const int r = idx / 50, f = (idx % 50) * 2;
        float2 a = *reinterpret_cast<const float2*>(&oS[r * 104 + f]);
        float2 bf = *reinterpret_cast<const float2*>(&biasS[f]);
        float2 o;
        o.x = fmaxf(a.x + bf.x, 0.f);
        o.y = fmaxf(a.y + bf.y, 0.f);
        *reinterpret_cast<float2*>(&out[((size_t)(b0 + r) * N_INST + i) * N_FEAT + f]) = o;
    }
}

// ---------------------------------------------------------------------------
extern "C" void kernel_launch(void* const* d_in, const int* in_sizes, int n_in,
                              void* d_out, int out_size) {
    (void)in_sizes; (void)n_in; (void)out_size;
    const float* x    = (const float*)d_in[0];
    const float* mask = (const float*)d_in[1];
    const float* A    = (const float*)d_in[2];
    const float* Bp   = (const float*)d_in[3];
    const float* bfin = (const float*)d_in[4];
    float* out = (float*)d_out;

    cudaFuncSetAttribute(tmsspd_main_kernel,
                         cudaFuncAttributeMaxDynamicSharedMemorySize, SM_TOTAL);

    compute_G_kernel<<<N_INST * NC, 256>>>(A, Bp);

    dim3 grid(B_SZ / 128, N_INST);
    tmsspd_main_kernel<<<grid, NTHR, SM_TOTAL>>>(x, mask, bfin, out);
}